// round 1
// baseline (speedup 1.0000x reference)
#include <cuda_runtime.h>
#include <math.h>

#define EPSF  1e-5f
#define MAXN  0.99999f
#define NQ    2048
#define HID   1024
#define DD    256
#define MM    65536
#define KNN   16
#define NSLICE 16
#define MSL   (MM / NSLICE)
#define QB    64
#define MT    64
#define KCH   32
#define FINF  3.402823466e38f

// ---------------- device scratch (no cudaMalloc allowed) ----------------
__device__ float g_tmp1[NQ * DD];
__device__ float g_G[NQ * DD];
__device__ float g_tmp2[NQ * DD];
__device__ float g_qb[NQ * DD];
__device__ float g_x2[NQ];
__device__ float g_omx2[NQ];
__device__ float g_mb[(size_t)MM * DD];   // 64 MB projected memory bank
__device__ float g_y2[MM];
__device__ float g_omy2[MM];
__device__ float g_pkey[NQ * NSLICE * KNN];
__device__ int   g_pidx[NQ * NSLICE * KNN];
__device__ float g_ret[NQ * DD];
__device__ float g_tmp3[NQ * HID];

// ---------------- helpers ----------------
__device__ __forceinline__ float blockReduceSum256(float v) {
    __shared__ float sred[8];
    #pragma unroll
    for (int o = 16; o > 0; o >>= 1) v += __shfl_down_sync(0xffffffffu, v, o);
    int w = threadIdx.x >> 5;
    if ((threadIdx.x & 31) == 0) sred[w] = v;
    __syncthreads();
    if (threadIdx.x < 32) {
        float r = (threadIdx.x < 8) ? sred[threadIdx.x] : 0.0f;
        #pragma unroll
        for (int o = 4; o > 0; o >>= 1) r += __shfl_down_sync(0xffffffffu, r, o);
        if (threadIdx.x == 0) sred[0] = r;
    }
    __syncthreads();
    float r = sred[0];
    __syncthreads();   // protect sred reuse by a following reduction
    return r;
}

// ---------------- generic 64x64 tiled fp32 GEMM: C = A[MxK] @ B[KxN] ----------------
__global__ void __launch_bounds__(256) gemm64x64(
    const float* __restrict__ A, const float* __restrict__ B,
    float* __restrict__ C, int M, int N, int Kd)
{
    __shared__ float As[KCH * 68];
    __shared__ float Bs[KCH * 68];
    int tid = threadIdx.x;
    int tx = tid & 15, ty = tid >> 4;
    int m0 = blockIdx.x * 64, n0 = blockIdx.y * 64;
    float acc[4][4] = {};
    for (int k0 = 0; k0 < Kd; k0 += KCH) {
        for (int i = tid; i < 64 * KCH; i += 256) {
            int m = i >> 5, k = i & 31;
            As[k * 68 + m] = A[(size_t)(m0 + m) * Kd + k0 + k];
        }
        for (int i = tid; i < KCH * 64; i += 256) {
            int k = i >> 6, n = i & 63;
            Bs[k * 68 + n] = B[(size_t)(k0 + k) * N + n0 + n];
        }
        __syncthreads();
        #pragma unroll
        for (int k = 0; k < KCH; k++) {
            float4 bv = *(const float4*)&Bs[k * 68 + tx * 4];
            float4 av = *(const float4*)&As[k * 68 + ty * 4];
            acc[0][0] += av.x * bv.x; acc[0][1] += av.x * bv.y; acc[0][2] += av.x * bv.z; acc[0][3] += av.x * bv.w;
            acc[1][0] += av.y * bv.x; acc[1][1] += av.y * bv.y; acc[1][2] += av.y * bv.z; acc[1][3] += av.y * bv.w;
            acc[2][0] += av.z * bv.x; acc[2][1] += av.z * bv.y; acc[2][2] += av.z * bv.z; acc[2][3] += av.z * bv.w;
            acc[3][0] += av.w * bv.x; acc[3][1] += av.w * bv.y; acc[3][2] += av.w * bv.z; acc[3][3] += av.w * bv.w;
        }
        __syncthreads();
    }
    #pragma unroll
    for (int i = 0; i < 4; i++) {
        float4 r = make_float4(acc[i][0], acc[i][1], acc[i][2], acc[i][3]);
        *(float4*)&C[(size_t)(m0 + ty * 4 + i) * N + n0 + tx * 4] = r;
    }
}

// ---------------- LayerNorm + exact GELU (one block per row of 256) ----------------
__global__ void ln_gelu_kernel(const float* __restrict__ X, const float* __restrict__ b1,
                               const float* __restrict__ g, const float* __restrict__ b,
                               float* __restrict__ G)
{
    int row = blockIdx.x, t = threadIdx.x;
    float v = X[(size_t)row * DD + t] + b1[t];
    float mu = blockReduceSum256(v) * (1.0f / DD);
    float d = v - mu;
    float var = blockReduceSum256(d * d) * (1.0f / DD);
    float y = d * rsqrtf(var + EPSF) * g[t] + b[t];
    G[(size_t)row * DD + t] = 0.5f * y * (1.0f + erff(y * 0.7071067811865476f));
}

// ---------------- add bias + Poincare projection for queries ----------------
__global__ void projq_kernel(const float* __restrict__ X, const float* __restrict__ b2,
                             float* __restrict__ qb, float* __restrict__ x2o,
                             float* __restrict__ omx2o)
{
    int row = blockIdx.x, t = threadIdx.x;
    float v = X[(size_t)row * DD + t] + b2[t];
    float ss = blockReduceSum256(v * v);
    float norm = sqrtf(ss);
    float scale = (norm > MAXN) ? (MAXN / fmaxf(norm, EPSF)) : 1.0f;
    float y = v * scale;
    qb[(size_t)row * DD + t] = y;
    float y2 = blockReduceSum256(y * y);
    if (t == 0) { x2o[row] = y2; omx2o[row] = 1.0f - y2; }
}

// ---------------- memory bank projection ----------------
__global__ void memprep_kernel(const float* __restrict__ mem, float* __restrict__ mb,
                               float* __restrict__ y2o, float* __restrict__ omy2o)
{
    int row = blockIdx.x, t = threadIdx.x;
    float v = mem[(size_t)row * DD + t];
    float ss = blockReduceSum256(v * v);
    float norm = sqrtf(ss);
    float scale = (norm > MAXN) ? (MAXN / fmaxf(norm, EPSF)) : 1.0f;
    float y = v * scale;
    mb[(size_t)row * DD + t] = y;
    float y2 = blockReduceSum256(y * y);
    if (t == 0) { y2o[row] = y2; omy2o[row] = 1.0f - y2; }
}

// ---------------- fused distance-GEMM + per-query top-K (per M slice) ----------------
// key = max(x2+y2-2xy, 0) / max((1-x2)(1-y2), EPS)  is a monotone surrogate for dist.
__global__ void __launch_bounds__(256, 2) topk_kernel(
    const float* __restrict__ qbp, const float* __restrict__ x2p, const float* __restrict__ omx2p,
    const float* __restrict__ mbp, const float* __restrict__ y2p, const float* __restrict__ omy2p,
    float* __restrict__ pkey, int* __restrict__ pidx)
{
    extern __shared__ float sm[];
    float* qsT  = sm;                   // [256][68] transposed query block
    float* msT  = qsT + 256 * 68;       // [32][68]  transposed memory k-chunk
    float* keyb = msT + 32 * 68;        // [64][68]  keys of current 64x64 tile
    float* lkey = keyb + 64 * 68;       // [64][16]  sorted top-K keys
    int*   lidx = (int*)(lkey + 64 * KNN);
    float* sx2   = (float*)(lidx + 64 * KNN);
    float* somx2 = sx2 + 64;
    float* sy2   = somx2 + 64;
    float* somy2 = sy2 + 64;

    int tid = threadIdx.x;
    int tx = tid & 15, ty = tid >> 4;
    int q0 = blockIdx.x * QB;
    int mbase = blockIdx.y * MSL;

    for (int i = tid; i < QB * DD; i += 256) {
        int q = i >> 8, k = i & 255;
        qsT[k * 68 + q] = qbp[(size_t)(q0 + q) * DD + k];
    }
    if (tid < QB) {
        sx2[tid] = x2p[q0 + tid];
        somx2[tid] = omx2p[q0 + tid];
        #pragma unroll
        for (int j = 0; j < KNN; j++) { lkey[tid * KNN + j] = FINF; lidx[tid * KNN + j] = 0; }
    }
    __syncthreads();

    for (int mt = 0; mt < MSL; mt += MT) {
        const float* Mrow = mbp + (size_t)(mbase + mt) * DD;
        float acc[4][4] = {};
        for (int kc = 0; kc < DD; kc += KCH) {
            __syncthreads();   // previous chunk's compute / previous tile's scan done
            for (int i = tid; i < MT * KCH; i += 256) {
                int m = i >> 5, k = i & 31;
                msT[k * 68 + m] = Mrow[(size_t)m * DD + kc + k];
            }
            if (kc == 0 && tid < MT) {
                sy2[tid]   = y2p[mbase + mt + tid];
                somy2[tid] = omy2p[mbase + mt + tid];
            }
            __syncthreads();
            #pragma unroll
            for (int k = 0; k < KCH; k++) {
                float4 mv = *(const float4*)&msT[k * 68 + tx * 4];
                float4 qv = *(const float4*)&qsT[(kc + k) * 68 + ty * 4];
                acc[0][0] += qv.x * mv.x; acc[0][1] += qv.x * mv.y; acc[0][2] += qv.x * mv.z; acc[0][3] += qv.x * mv.w;
                acc[1][0] += qv.y * mv.x; acc[1][1] += qv.y * mv.y; acc[1][2] += qv.y * mv.z; acc[1][3] += qv.y * mv.w;
                acc[2][0] += qv.z * mv.x; acc[2][1] += qv.z * mv.y; acc[2][2] += qv.z * mv.z; acc[2][3] += qv.z * mv.w;
                acc[3][0] += qv.w * mv.x; acc[3][1] += qv.w * mv.y; acc[3][2] += qv.w * mv.z; acc[3][3] += qv.w * mv.w;
            }
        }
        // compute keys into smem tile
        #pragma unroll
        for (int i = 0; i < 4; i++) {
            int q = ty * 4 + i;
            float x2v = sx2[q], omx2v = somx2[q];
            #pragma unroll
            for (int jj = 0; jj < 4; jj++) {
                int m = tx * 4 + jj;
                float sq  = fmaxf(x2v + sy2[m] - 2.0f * acc[i][jj], 0.0f);
                float den = fmaxf(omx2v * somy2[m], EPSF);
                keyb[q * 68 + m] = sq / den;
            }
        }
        __syncthreads();
        // per-query sorted top-K update (thread per query; inserts are rare)
        if (tid < QB) {
            float worst = lkey[tid * KNN + KNN - 1];
            for (int m = 0; m < MT; m++) {
                float kv = keyb[tid * 68 + m];
                if (kv < worst) {
                    int pos = KNN - 1;
                    while (pos > 0 && lkey[tid * KNN + pos - 1] > kv) {
                        lkey[tid * KNN + pos] = lkey[tid * KNN + pos - 1];
                        lidx[tid * KNN + pos] = lidx[tid * KNN + pos - 1];
                        pos--;
                    }
                    lkey[tid * KNN + pos] = kv;
                    lidx[tid * KNN + pos] = mbase + mt + m;
                    worst = lkey[tid * KNN + KNN - 1];
                }
            }
        }
        __syncthreads();
    }
    for (int i = tid; i < QB * KNN; i += 256) {
        int q = i / KNN, j = i % KNN;
        int o = ((q0 + q) * NSLICE + blockIdx.y) * KNN + j;
        pkey[o] = lkey[i];
        pidx[o] = lidx[i];
    }
}

// ---------------- merge partial top-K, arccosh, softmax, gather retrieved ----------------
__global__ void merge_kernel(const float* __restrict__ pkey, const int* __restrict__ pidx,
                             const float* __restrict__ mb, float* __restrict__ ret)
{
    int q = blockIdx.x, t = threadIdx.x;
    __shared__ float skey[256];
    __shared__ int   sidx[256];
    __shared__ float wkey[KNN];
    __shared__ int   widx[KNN];
    __shared__ float wgt[KNN];

    float myk = pkey[(size_t)q * 256 + t];
    int   myi = pidx[(size_t)q * 256 + t];

    for (int j = 0; j < KNN; j++) {
        skey[t] = myk; sidx[t] = myi;
        __syncthreads();
        for (int s = 128; s > 0; s >>= 1) {
            if (t < s) {
                float k2 = skey[t + s]; int i2 = sidx[t + s];
                if (k2 < skey[t] || (k2 == skey[t] && i2 < sidx[t])) { skey[t] = k2; sidx[t] = i2; }
            }
            __syncthreads();
        }
        if (t == 0) { wkey[j] = skey[0]; widx[j] = sidx[0]; }
        __syncthreads();
        if (myi == widx[j]) myk = FINF;   // indices globally unique
    }

    if (t == 0) {
        float dv[KNN];
        #pragma unroll
        for (int j = 0; j < KNN; j++) {
            float arg = fmaxf(1.0f + 2.0f * wkey[j], 1.0f + EPSF);
            dv[j] = logf(arg + sqrtf(arg * arg - 1.0f));    // arccosh
        }
        float dmin = dv[0];
        #pragma unroll
        for (int j = 1; j < KNN; j++) dmin = fminf(dmin, dv[j]);
        float s = 0.0f;
        #pragma unroll
        for (int j = 0; j < KNN; j++) { float e = expf(dmin - dv[j]); wgt[j] = e; s += e; }
        float inv = 1.0f / s;
        #pragma unroll
        for (int j = 0; j < KNN; j++) wgt[j] *= inv;
    }
    __syncthreads();

    float acc = 0.0f;
    #pragma unroll
    for (int j = 0; j < KNN; j++) acc += wgt[j] * mb[(size_t)widx[j] * DD + t];
    ret[(size_t)q * DD + t] = acc;
}

// ---------------- residual epilogue ----------------
__global__ void final_kernel(const float* __restrict__ hidden, const float* __restrict__ go,
                             const float* __restrict__ bp, float* __restrict__ out)
{
    int i = blockIdx.x * 256 + threadIdx.x;
    out[i] = hidden[i] + 0.1f * (go[i] + bp[i & (HID - 1)]);
}

// ---------------- launcher ----------------
extern "C" void kernel_launch(void* const* d_in, const int* in_sizes, int n_in,
                              void* d_out, int out_size)
{
    const float* hidden = (const float*)d_in[0];
    const float* memory = (const float*)d_in[1];
    const float* w1     = (const float*)d_in[2];
    const float* b1     = (const float*)d_in[3];
    const float* ln_g   = (const float*)d_in[4];
    const float* ln_b   = (const float*)d_in[5];
    const float* w2     = (const float*)d_in[6];
    const float* b2     = (const float*)d_in[7];
    const float* wp     = (const float*)d_in[8];
    const float* bp     = (const float*)d_in[9];
    float* out = (float*)d_out;

    float *tmp1, *G, *tmp2, *qb, *x2, *omx2, *mb, *y2, *omy2, *pkey, *ret, *tmp3;
    int* pidx;
    cudaGetSymbolAddress((void**)&tmp1, g_tmp1);
    cudaGetSymbolAddress((void**)&G,    g_G);
    cudaGetSymbolAddress((void**)&tmp2, g_tmp2);
    cudaGetSymbolAddress((void**)&qb,   g_qb);
    cudaGetSymbolAddress((void**)&x2,   g_x2);
    cudaGetSymbolAddress((void**)&omx2, g_omx2);
    cudaGetSymbolAddress((void**)&mb,   g_mb);
    cudaGetSymbolAddress((void**)&y2,   g_y2);
    cudaGetSymbolAddress((void**)&omy2, g_omy2);
    cudaGetSymbolAddress((void**)&pkey, g_pkey);
    cudaGetSymbolAddress((void**)&pidx, g_pidx);
    cudaGetSymbolAddress((void**)&ret,  g_ret);
    cudaGetSymbolAddress((void**)&tmp3, g_tmp3);

    const int SMEMB = (256 * 68 + 32 * 68 + 64 * 68 + 64 * KNN) * 4 + 64 * KNN * 4 + 4 * 64 * 4;
    cudaFuncSetAttribute(topk_kernel, cudaFuncAttributeMaxDynamicSharedMemorySize, SMEMB);

    // query network
    gemm64x64<<<dim3(NQ / 64, DD / 64), 256>>>(hidden, w1, tmp1, NQ, DD, HID);
    ln_gelu_kernel<<<NQ, 256>>>(tmp1, b1, ln_g, ln_b, G);
    gemm64x64<<<dim3(NQ / 64, DD / 64), 256>>>(G, w2, tmp2, NQ, DD, DD);
    projq_kernel<<<NQ, 256>>>(tmp2, b2, qb, x2, omx2);

    // memory bank projection
    memprep_kernel<<<MM, 256>>>(memory, mb, y2, omy2);

    // fused distance + top-K over M slices
    topk_kernel<<<dim3(NQ / QB, NSLICE), 256, SMEMB>>>(qb, x2, omx2, mb, y2, omy2, pkey, pidx);

    // merge + softmax + weighted gather
    merge_kernel<<<NQ, 256>>>(pkey, pidx, mb, ret);

    // project back + residual
    gemm64x64<<<dim3(NQ / 64, HID / 64), 256>>>(ret, wp, tmp3, NQ, HID, DD);
    final_kernel<<<NQ * HID / 256, 256>>>(hidden, tmp3, bp, out);
}